// round 5
// baseline (speedup 1.0000x reference)
#include <cuda_runtime.h>

typedef unsigned long long ull;

#define Bsz   128
#define TM1   255
#define NIN   256
#define Hd    256
#define BT    (Bsz * TM1)      /* 32640 */
#define G4H   1024

// ---------------- device scratch (static allocation only) ----------------
__device__ float g_G[(size_t)BT * G4H];   // 133.7 MB: x_tilde@W + b

// ---------------- packed f32x2 helpers -----------------------------------
__device__ __forceinline__ ull pack2(float lo, float hi) {
    ull r; asm("mov.b64 %0, {%1, %2};" : "=l"(r) : "f"(lo), "f"(hi)); return r;
}
__device__ __forceinline__ float2 unpack2(ull v) {
    float2 r; asm("mov.b64 {%0, %1}, %2;" : "=f"(r.x), "=f"(r.y) : "l"(v)); return r;
}
#define FFMA2(acc, a, b) asm("fma.rn.f32x2 %0, %1, %2, %0;" : "+l"(acc) : "l"(a), "l"(b))
__device__ __forceinline__ ull add2(ull a, ull b) {
    ull r; asm("add.rn.f32x2 %0, %1, %2;" : "=l"(r) : "l"(a), "l"(b)); return r;
}
struct __align__(16) ull2_t { ull x, y; };

__device__ __forceinline__ unsigned smem_u32(const void* p) {
    unsigned r;
    asm("{ .reg .u64 t; cvta.to.shared.u64 t, %1; cvt.u32.u64 %0, t; }"
        : "=r"(r) : "l"(p));
    return r;
}
__device__ __forceinline__ unsigned mapa_u32(unsigned a, unsigned rk) {
    unsigned o; asm("mapa.shared::cluster.u32 %0, %1, %2;" : "=r"(o) : "r"(a), "r"(rk));
    return o;
}
__device__ __forceinline__ void st_remote_f32(unsigned a, float v) {
    asm volatile("st.shared::cluster.f32 [%0], %1;" :: "r"(a), "f"(v) : "memory");
}
#define CLUSTER_SYNC() do { \
    asm volatile("barrier.cluster.arrive.aligned;" ::: "memory"); \
    asm volatile("barrier.cluster.wait.aligned;"   ::: "memory"); } while (0)

__device__ __forceinline__ float sigm(float x) { return 1.f / (1.f + expf(-x)); }

// ---------------- kernel 1: alpha (softmax over inputs) + X_tilde --------
// alpha[b,n] = softmax_n( sum_t X[b,t,n] * W_attn[2H + t] )  (h/c/b_attn terms
// are constant over n and cancel in the softmax).
__global__ __launch_bounds__(256) void alpha_kernel(const float* __restrict__ X,
                                                    const float* __restrict__ W_attn,
                                                    float* __restrict__ out_xt) {
    __shared__ float wx[TM1];
    __shared__ float red[256];
    const int b = blockIdx.x;
    const int n = threadIdx.x;
    if (n < TM1) wx[n] = W_attn[2 * Hd + n];
    __syncthreads();

    const float* Xb = X + (size_t)b * TM1 * NIN;
    float e = 0.f;
#pragma unroll 5
    for (int t = 0; t < TM1; t++) e = fmaf(Xb[t * NIN + n], wx[t], e);

    red[n] = e; __syncthreads();
    for (int s = 128; s > 0; s >>= 1) {
        if (n < s) red[n] = fmaxf(red[n], red[n + s]);
        __syncthreads();
    }
    float m = red[0];
    __syncthreads();
    float p = expf(e - m);
    red[n] = p; __syncthreads();
    for (int s = 128; s > 0; s >>= 1) {
        if (n < s) red[n] += red[n + s];
        __syncthreads();
    }
    const float a = p / red[0];

    float* outb = out_xt + (size_t)b * TM1 * NIN;
#pragma unroll 5
    for (int t = 0; t < TM1; t++) outb[t * NIN + n] = a * Xb[t * NIN + n];
}

// ---------------- kernel 2: G = X_tilde @ W_lstm + b_lstm (FFMA2) --------
__global__ __launch_bounds__(256, 2) void gemm_kernel(const float* __restrict__ A,
                                                      const float* __restrict__ W,
                                                      const float* __restrict__ bias) {
    __shared__ float As[8][128];
    __shared__ float Bs[8][128];
    const int tid  = threadIdx.x;
    const int row0 = blockIdx.y * 128;
    const int col0 = blockIdx.x * 128;

    ull accp[8][4];
#pragma unroll
    for (int i = 0; i < 8; i++)
#pragma unroll
        for (int jp = 0; jp < 4; jp++) accp[i][jp] = 0ULL;

    const int tr = (tid >> 4) << 3;
    const int tc = (tid & 15) << 3;
    const int am = tid >> 1,  ak = (tid & 1) << 2;
    const int bk = tid >> 5,  bc = (tid & 31) << 2;

    for (int k0 = 0; k0 < 256; k0 += 8) {
        float4 av = *(const float4*)(A + (size_t)(row0 + am) * 256 + k0 + ak);
        As[ak + 0][am] = av.x; As[ak + 1][am] = av.y;
        As[ak + 2][am] = av.z; As[ak + 3][am] = av.w;
        *(float4*)&Bs[bk][bc] = *(const float4*)(W + (size_t)(k0 + bk) * 1024 + col0 + bc);
        __syncthreads();
#pragma unroll
        for (int k = 0; k < 8; k++) {
            float a8[8];
            *(float4*)&a8[0] = *(const float4*)&As[k][tr];
            *(float4*)&a8[4] = *(const float4*)&As[k][tr + 4];
            double2 t0 = *(const double2*)&Bs[k][tc];
            double2 t1 = *(const double2*)&Bs[k][tc + 4];
            ull b4[4] = { __double_as_longlong(t0.x), __double_as_longlong(t0.y),
                          __double_as_longlong(t1.x), __double_as_longlong(t1.y) };
#pragma unroll
            for (int i = 0; i < 8; i++) {
                ull ap = pack2(a8[i], a8[i]);
#pragma unroll
                for (int jp = 0; jp < 4; jp++) FFMA2(accp[i][jp], ap, b4[jp]);
            }
        }
        __syncthreads();
    }

    float bias8[8];
    *(float4*)&bias8[0] = *(const float4*)&bias[col0 + tc];
    *(float4*)&bias8[4] = *(const float4*)&bias[col0 + tc + 4];
#pragma unroll
    for (int i = 0; i < 8; i++) {
        const size_t r = (size_t)(row0 + tr + i) * G4H + col0 + tc;
        float2 v0 = unpack2(accp[i][0]), v1 = unpack2(accp[i][1]);
        float2 v2 = unpack2(accp[i][2]), v3 = unpack2(accp[i][3]);
        float4 o1 = { v0.x + bias8[0], v0.y + bias8[1], v1.x + bias8[2], v1.y + bias8[3] };
        float4 o2 = { v2.x + bias8[4], v2.y + bias8[5], v3.x + bias8[6], v3.y + bias8[7] };
        *(float4*)&g_G[r]     = o1;
        *(float4*)&g_G[r + 4] = o2;
    }
}

// ---------------- kernel 3: cluster-based LSTM recurrence ----------------
// 128 CTAs = 16 clusters of 8. Cluster = one b-block (8 batches); rank = j-block
// (32 hidden units). h exchanged via DSMEM + barrier.cluster each step.
// Thread decomposition: jj = lane (j), bg = batch-group of 4, kq = k-quarter.
// Batch pairs packed in f32x2; per-16B-of-U we now do 16 FMAs (8 FFMA2).
#define RSMEM_US   131072                    /* float4[256*32] U slice        */
#define RSMEM_HB   16384                     /* float[2][2048] h double-buf   */
#define RSMEM_RED  12288                     /* ull[8][192] k-partial sums    */
#define RSMEM_BYTES (RSMEM_US + RSMEM_HB + RSMEM_RED)

__global__ void __launch_bounds__(256, 1) __cluster_dims__(8, 1, 1)
recur_kernel(const float* __restrict__ X,
             const float* __restrict__ U,
             float* __restrict__ out_enc) {
    extern __shared__ char smem[];
    float4* Us4  = (float4*)smem;                       // [k*32 + jj] -> gates i,f,g,o
    float*  hbuf = (float*)(smem + RSMEM_US);           // [buf][bp*512 + k*2 + e]
    ull*    red  = (ull*)(smem + RSMEM_US + RSMEM_HB);  // [i*192 + (kq-1)*64 + pos]

    const int tid = threadIdx.x;
    const int jj  = tid & 31;
    const int bg  = (tid >> 5) & 1;      // batch group: batches bg*4 .. bg*4+3
    const int kq  = tid >> 6;            // k quarter: [kq*64, kq*64+64)
    unsigned rank; asm("mov.u32 %0, %%cluster_ctarank;" : "=r"(rank));
    const int j0 = (int)rank * 32;
    const int b0 = (blockIdx.x >> 3) * 8;
    const int j  = j0 + jj;
    const int bp0 = bg * 2, bp1 = bg * 2 + 1;

    // Load U slice once (coalesced per warp, conflict-free)
    for (int idx = tid; idx < 256 * 32; idx += 256) {
        const int k  = idx >> 5;
        const int jc = j0 + (idx & 31);
        const float* Uk = U + (size_t)k * 1024;
        Us4[idx] = make_float4(Uk[jc], Uk[jc + 256], Uk[jc + 512], Uk[jc + 768]);
    }
    // init h0 = c0 = X[b,0,0] broadcast; pair-interleaved layout
    for (int idx = tid; idx < 2048; idx += 256) {
        const int bp = idx >> 9;
        const int e  = idx & 1;
        hbuf[idx] = X[(size_t)(b0 + bp * 2 + e) * (TM1 * NIN)];
    }
    float cst[2][2];
    if (kq == 0) {
#pragma unroll
        for (int p = 0; p < 2; p++)
#pragma unroll
            for (int e = 0; e < 2; e++)
                cst[p][e] = X[(size_t)(b0 + bg * 4 + 2 * p + e) * (TM1 * NIN)];
    }
    __syncthreads();
    CLUSTER_SYNC();   // all smem init (incl. peers') done before DSMEM traffic

    for (int t = 0; t < TM1; t++) {
        const float* hb      = hbuf + (t & 1) * 2048;
        float*       hn_base = hbuf + ((t + 1) & 1) * 2048;

        // prefetch this step's G values (global, coalesced across jj)
        float Gr[2][2][4];
        if (kq == 0) {
#pragma unroll
            for (int p = 0; p < 2; p++)
#pragma unroll
                for (int e = 0; e < 2; e++) {
                    const float* gr = g_G + ((size_t)(b0 + bg * 4 + 2 * p + e) * TM1 + t) * G4H + j;
                    Gr[p][e][0] = gr[0];   Gr[p][e][1] = gr[256];
                    Gr[p][e][2] = gr[512]; Gr[p][e][3] = gr[768];
                }
        }

        // partial h@U over this thread's k-quarter, batch pairs packed f32x2
        ull acc2[2][4];
#pragma unroll
        for (int p = 0; p < 2; p++)
#pragma unroll
            for (int g = 0; g < 4; g++) acc2[p][g] = 0ULL;

        const float4* up  = Us4 + kq * 64 * 32 + jj;
        const ull2_t* hpA = (const ull2_t*)(hb + bp0 * 512) + kq * 32;
        const ull2_t* hpB = (const ull2_t*)(hb + bp1 * 512) + kq * 32;
#pragma unroll 4
        for (int m = 0; m < 32; m++) {
            const float4 u0 = up[(2 * m) * 32];
            const float4 u1 = up[(2 * m + 1) * 32];
            const ull2_t h0 = hpA[m];       // pairs {h[2bp0],h[2bp0+1]} for k, k+1
            const ull2_t h1 = hpB[m];
            ull ux, uy, uz, uw;
            ux = pack2(u0.x, u0.x); uy = pack2(u0.y, u0.y);
            uz = pack2(u0.z, u0.z); uw = pack2(u0.w, u0.w);
            FFMA2(acc2[0][0], h0.x, ux); FFMA2(acc2[0][1], h0.x, uy);
            FFMA2(acc2[0][2], h0.x, uz); FFMA2(acc2[0][3], h0.x, uw);
            FFMA2(acc2[1][0], h1.x, ux); FFMA2(acc2[1][1], h1.x, uy);
            FFMA2(acc2[1][2], h1.x, uz); FFMA2(acc2[1][3], h1.x, uw);
            ux = pack2(u1.x, u1.x); uy = pack2(u1.y, u1.y);
            uz = pack2(u1.z, u1.z); uw = pack2(u1.w, u1.w);
            FFMA2(acc2[0][0], h0.y, ux); FFMA2(acc2[0][1], h0.y, uy);
            FFMA2(acc2[0][2], h0.y, uz); FFMA2(acc2[0][3], h0.y, uw);
            FFMA2(acc2[1][0], h1.y, ux); FFMA2(acc2[1][1], h1.y, uy);
            FFMA2(acc2[1][2], h1.y, uz); FFMA2(acc2[1][3], h1.y, uw);
        }

        // k-quarter reduction through smem
        if (kq) {
            const int pos = tid & 63;
#pragma unroll
            for (int p = 0; p < 2; p++)
#pragma unroll
                for (int g = 0; g < 4; g++)
                    red[(p * 4 + g) * 192 + (kq - 1) * 64 + pos] = acc2[p][g];
        }
        __syncthreads();

        if (kq == 0) {
            const int pos = tid;   // tid < 64 here
            float z[2][4][2];
#pragma unroll
            for (int p = 0; p < 2; p++)
#pragma unroll
                for (int g = 0; g < 4; g++) {
                    ull s = acc2[p][g];
                    s = add2(s, red[(p * 4 + g) * 192 + pos]);
                    s = add2(s, red[(p * 4 + g) * 192 + 64 + pos]);
                    s = add2(s, red[(p * 4 + g) * 192 + 128 + pos]);
                    float2 f = unpack2(s);
                    z[p][g][0] = f.x; z[p][g][1] = f.y;
                }

            const unsigned nb_u32 = smem_u32(hn_base);
#pragma unroll
            for (int p = 0; p < 2; p++)
#pragma unroll
                for (int e = 0; e < 2; e++) {
                    const float zi = z[p][0][e] + Gr[p][e][0];
                    const float zf = z[p][1][e] + Gr[p][e][1];
                    const float zg = z[p][2][e] + Gr[p][e][2];
                    const float zo = z[p][3][e] + Gr[p][e][3];
                    const float cc = sigm(zf) * cst[p][e] + sigm(zi) * tanhf(zg);
                    cst[p][e] = cc;
                    const float hn = sigm(zo) * tanhf(cc);
                    out_enc[((size_t)(b0 + bg * 4 + 2 * p + e) * TM1 + t) * Hd + j] = hn;
                    // broadcast h to every rank's next-buffer (incl. self)
                    const unsigned off = (unsigned)(((bg * 2 + p) * 512 + j * 2 + e) * 4);
#pragma unroll
                    for (unsigned r = 0; r < 8; r++)
                        st_remote_f32(mapa_u32(nb_u32 + off, r), hn);
                }
        }

        CLUSTER_SYNC();   // release h_{t+1} writes; acquire before next reads
    }
}

// ---------------- launch ----------------
extern "C" void kernel_launch(void* const* d_in, const int* in_sizes, int n_in,
                              void* d_out, int out_size) {
    const float* X      = (const float*)d_in[0];
    const float* W_attn = (const float*)d_in[1];
    /* b_attn = d_in[2] : cancels in softmax */
    const float* W_lstm = (const float*)d_in[3];
    const float* U_lstm = (const float*)d_in[4];
    const float* b_lstm = (const float*)d_in[5];

    float* out     = (float*)d_out;
    float* out_xt  = out;                             // X_tilde  (B,Tm1,N)
    float* out_enc = out + (size_t)Bsz * TM1 * NIN;   // X_encoded (B,Tm1,H)

    cudaFuncSetAttribute(recur_kernel,
                         cudaFuncAttributeMaxDynamicSharedMemorySize, RSMEM_BYTES);

    alpha_kernel<<<Bsz, 256>>>(X, W_attn, out_xt);
    gemm_kernel<<<dim3(8, TM1), 256>>>(out_xt, W_lstm, b_lstm);
    recur_kernel<<<128, 256, RSMEM_BYTES>>>(X, U_lstm, out_enc);
}